// round 10
// baseline (speedup 1.0000x reference)
#include <cuda_runtime.h>
#include <cstdint>

#define NN 100000
#define NE 1600000
#define IN_CH 256
#define HID 128
#define OUT_CH 64

#define SCH 1024                       // elements per scan chunk
#define NCHK ((NN + SCH - 1) / SCH)    // 98 chunks

// Scratch (device globals: allocation-free per harness rules)
__device__ float g_h[(size_t)NN * HID];       // 51.2 MB
__device__ int   g_deg[NN];
__device__ int   g_row_off[NN + 1];
__device__ int   g_cursor[NN];
__device__ int   g_csr_src[NE];
__device__ int   g_part[NCHK];

// ---------------- packed f32x2 helpers (Blackwell dual-fp32 pipe) ----------------
__device__ __forceinline__ unsigned long long pack2(float lo, float hi) {
    unsigned long long r;
    asm("mov.b64 %0, {%1, %2};" : "=l"(r) : "f"(lo), "f"(hi));
    return r;
}
__device__ __forceinline__ void fma2(unsigned long long& d, unsigned long long a,
                                     unsigned long long b) {
    asm("fma.rn.f32x2 %0, %1, %2, %3;" : "=l"(d) : "l"(a), "l"(b), "l"(d));
}

// ---------------------------------------------------------------------------
// SGEMM (R2 structure, f32x2 inner loop): C[M,N] = A[M,K] @ B[K,N].
// BM=128, BN=N, BK=8, 256 threads, per-thread micro-tile 8 x (N/16).
// ---------------------------------------------------------------------------
template <int K, int N>
__global__ void __launch_bounds__(256) sgemm_kernel(const float* __restrict__ A,
                                                    const float* __restrict__ B,
                                                    float* __restrict__ C, int M)
{
    constexpr int BM = 128, BN = N, BK = 8;
    constexpr int TM = 8, TN = BN / 16;          // 8 or 4
    constexpr int TP = TN / 2;                   // packed pairs per row (4 or 2)
    __shared__ float As[BK][BM];
    __shared__ float Bs[BK][BN];

    const int tid = threadIdx.x;
    const int tx = tid & 15;                     // col group
    const int ty = tid >> 4;                     // row group
    const int row0 = blockIdx.x * BM;

    unsigned long long accp[TM][TP];
#pragma unroll
    for (int i = 0; i < TM; i++)
#pragma unroll
        for (int j = 0; j < TP; j++) accp[i][j] = 0ull;   // {0.f, 0.f}

    // A-load mapping: thread -> (row = tid/2, kk4 = (tid&1)*4), float4 along K
    const int ar = tid >> 1;
    const int ak = (tid & 1) * 4;

    for (int k0 = 0; k0 < K; k0 += BK) {
        // Stage A tile (transposed into As[kk][row])
        {
            int gr = row0 + ar;
            float4 v = make_float4(0.f, 0.f, 0.f, 0.f);
            if (gr < M)
                v = *reinterpret_cast<const float4*>(&A[(size_t)gr * K + k0 + ak]);
            As[ak + 0][ar] = v.x;
            As[ak + 1][ar] = v.y;
            As[ak + 2][ar] = v.z;
            As[ak + 3][ar] = v.w;
        }
        // Stage B tile: BK*BN floats, float4 per thread
        {
            int idx = tid * 4;
            if (idx < BK * BN) {
                int kk = idx / BN, c = idx % BN;
                *reinterpret_cast<float4*>(&Bs[kk][c]) =
                    *reinterpret_cast<const float4*>(&B[(size_t)(k0 + kk) * N + c]);
            }
        }
        __syncthreads();

#pragma unroll
        for (int kk = 0; kk < BK; kk++) {
            // A values (8 rows), duplicated into pairs for f32x2 broadcast
            float4 a0 = *reinterpret_cast<const float4*>(&As[kk][ty * TM]);
            float4 a1 = *reinterpret_cast<const float4*>(&As[kk][ty * TM + 4]);
            unsigned long long ap[TM];
            ap[0] = pack2(a0.x, a0.x); ap[1] = pack2(a0.y, a0.y);
            ap[2] = pack2(a0.z, a0.z); ap[3] = pack2(a0.w, a0.w);
            ap[4] = pack2(a1.x, a1.x); ap[5] = pack2(a1.y, a1.y);
            ap[6] = pack2(a1.z, a1.z); ap[7] = pack2(a1.w, a1.w);
            // B pairs (TN contiguous cols -> TP 64-bit pairs)
            unsigned long long bp[TP];
#pragma unroll
            for (int j = 0; j < TP; j++)
                bp[j] = *reinterpret_cast<const unsigned long long*>(
                            &Bs[kk][tx * TN + 2 * j]);
#pragma unroll
            for (int i = 0; i < TM; i++)
#pragma unroll
                for (int j = 0; j < TP; j++)
                    fma2(accp[i][j], ap[i], bp[j]);
        }
        __syncthreads();
    }

#pragma unroll
    for (int i = 0; i < TM; i++) {
        int gr = row0 + ty * TM + i;
        if (gr < M) {
            unsigned long long* cp =
                reinterpret_cast<unsigned long long*>(&C[(size_t)gr * N + tx * TN]);
#pragma unroll
            for (int j = 0; j < TP; j++) cp[j] = accp[i][j];
        }
    }
}

// ---------------------------------------------------------------------------
// CSR build: histogram -> 3-phase parallel exclusive scan -> cursor fill
// ---------------------------------------------------------------------------
__global__ void hist_kernel(const int* __restrict__ dst)
{
    int stride = gridDim.x * blockDim.x;
    for (int e = blockIdx.x * blockDim.x + threadIdx.x; e < NE; e += stride)
        atomicAdd(&g_deg[dst[e]], 1);
}

__global__ void __launch_bounds__(256) scan_partial_kernel()
{
    __shared__ int red[8];
    int b = blockIdx.x, t = threadIdx.x;
    int base = b * SCH;
    int sum = 0;
#pragma unroll
    for (int q = 0; q < SCH / 256; q++) {
        int i = base + q * 256 + t;
        if (i < NN) sum += g_deg[i];
    }
    for (int o = 16; o > 0; o >>= 1) sum += __shfl_down_sync(0xffffffffu, sum, o);
    if ((t & 31) == 0) red[t >> 5] = sum;
    __syncthreads();
    if (t < 8) {
        int v = red[t];
        for (int o = 4; o > 0; o >>= 1) v += __shfl_down_sync(0xffu, v, o);
        if (t == 0) g_part[b] = v;
    }
}

__global__ void __launch_bounds__(128) scan_chunks_kernel()
{
    __shared__ int s[128];
    int t = threadIdx.x;
    int v = (t < NCHK) ? g_part[t] : 0;
    s[t] = v;
    __syncthreads();
#pragma unroll
    for (int o = 1; o < 128; o <<= 1) {
        int u = (t >= o) ? s[t - o] : 0;
        __syncthreads();
        s[t] += u;
        __syncthreads();
    }
    if (t < NCHK) g_part[t] = s[t] - v;     // exclusive chunk base
    if (t == 127) g_row_off[NN] = s[127];   // total (== NE)
}

__global__ void __launch_bounds__(256) scan_write_kernel()
{
    __shared__ int s[256];
    int b = blockIdx.x, t = threadIdx.x;
    int i0 = b * SCH + t * 4;

    int4 d = make_int4(0, 0, 0, 0);
    if (i0 < NN) d = *reinterpret_cast<const int4*>(&g_deg[i0]);  // NN % 4 == 0
    int tsum = d.x + d.y + d.z + d.w;

    s[t] = tsum;
    __syncthreads();
#pragma unroll
    for (int o = 1; o < 256; o <<= 1) {
        int u = (t >= o) ? s[t - o] : 0;
        __syncthreads();
        s[t] += u;
        __syncthreads();
    }
    int base = g_part[b] + s[t] - tsum;     // exclusive within chunk

    if (i0 < NN) {
        int4 ro, cu;
        ro.x = base;             cu.x = ro.x;
        ro.y = ro.x + d.x;       cu.y = ro.y;
        ro.z = ro.y + d.y;       cu.z = ro.z;
        ro.w = ro.z + d.z;       cu.w = ro.w;
        *reinterpret_cast<int4*>(&g_row_off[i0]) = ro;
        *reinterpret_cast<int4*>(&g_cursor[i0]) = cu;
    }
}

__global__ void fill_kernel(const int* __restrict__ src, const int* __restrict__ dst)
{
    int stride = gridDim.x * blockDim.x;
    for (int e = blockIdx.x * blockDim.x + threadIdx.x; e < NE; e += stride) {
        int pos = atomicAdd(&g_cursor[dst[e]], 1);
        g_csr_src[pos] = src[e];
    }
}

// ---------------------------------------------------------------------------
// Gather aggregation: one warp per node; unroll-by-2 for MLP
// ---------------------------------------------------------------------------
__global__ void agg_kernel(const float* __restrict__ bias, float* __restrict__ out1)
{
    int warp = (blockIdx.x * blockDim.x + threadIdx.x) >> 5;
    int lane = threadIdx.x & 31;
    if (warp >= NN) return;

    const float4* h4 = reinterpret_cast<const float4*>(g_h);
    int s = g_row_off[warp];
    int e = g_row_off[warp + 1];

    float4 acc0 = make_float4(0.f, 0.f, 0.f, 0.f);
    float4 acc1 = make_float4(0.f, 0.f, 0.f, 0.f);
    int i = s;
    for (; i + 1 < e; i += 2) {
        int s0 = g_csr_src[i];
        int s1 = g_csr_src[i + 1];
        float4 v0 = h4[(size_t)s0 * (HID / 4) + lane];
        float4 v1 = h4[(size_t)s1 * (HID / 4) + lane];
        acc0.x += v0.x; acc0.y += v0.y; acc0.z += v0.z; acc0.w += v0.w;
        acc1.x += v1.x; acc1.y += v1.y; acc1.z += v1.z; acc1.w += v1.w;
    }
    if (i < e) {
        int s0 = g_csr_src[i];
        float4 v0 = h4[(size_t)s0 * (HID / 4) + lane];
        acc0.x += v0.x; acc0.y += v0.y; acc0.z += v0.z; acc0.w += v0.w;
    }
    float4 b = reinterpret_cast<const float4*>(bias)[lane];
    acc0.x += acc1.x + b.x; acc0.y += acc1.y + b.y;
    acc0.z += acc1.z + b.z; acc0.w += acc1.w + b.w;
    reinterpret_cast<float4*>(out1)[(size_t)warp * (HID / 4) + lane] = acc0;
}

// ---------------------------------------------------------------------------
extern "C" void kernel_launch(void* const* d_in, const int* in_sizes, int n_in,
                              void* d_out, int out_size)
{
    const float* x   = (const float*)d_in[0];
    const int* edge  = (const int*)d_in[1];
    const float* Wg  = (const float*)d_in[2];
    const float* bg  = (const float*)d_in[3];
    const float* W1  = (const float*)d_in[4];
    const float* W2  = (const float*)d_in[5];
    const int* src = edge;
    const int* dst = edge + NE;

    float* out  = (float*)d_out;
    float* out1 = out;                                  // [NN, HID]
    float* out2 = out1 + (size_t)NN * HID;              // [NN, HID]
    float* out3 = out2 + (size_t)NN * HID;              // [NN, OUT_CH]

    float* h = nullptr;
    cudaGetSymbolAddress((void**)&h, g_h);
    int* degPtr = nullptr;
    cudaGetSymbolAddress((void**)&degPtr, g_deg);

    const int M = NN;

    // 1) h = x @ W_gcn
    sgemm_kernel<IN_CH, HID><<<(M + 127) / 128, 256>>>(x, Wg, h, M);

    // 2) CSR build (parallel scan)
    cudaMemsetAsync(degPtr, 0, NN * sizeof(int));
    hist_kernel<<<1024, 256>>>(dst);
    scan_partial_kernel<<<NCHK, 256>>>();
    scan_chunks_kernel<<<1, 128>>>();
    scan_write_kernel<<<NCHK, 256>>>();
    fill_kernel<<<1024, 256>>>(src, dst);

    // 3) out1 = gather-sum + bias
    agg_kernel<<<(NN * 32 + 255) / 256, 256>>>(bg, out1);

    // 4) MLP
    sgemm_kernel<HID, HID><<<(M + 127) / 128, 256>>>(out1, W1, out2, M);
    sgemm_kernel<HID, OUT_CH><<<(M + 127) / 128, 256>>>(out2, W2, out3, M);
}